// round 11
// baseline (speedup 1.0000x reference)
#include <cuda_runtime.h>

// CharRNN: 3-layer tanh RNN, B=512, T=1024, HID=100, VOCAB=62.
// R11: R10 champion + in-warp k-split (lane = p*16+m, shfl_xor(16) exchange,
//      no scratch), 3 barriers/step (was 6), double-buffered h, balanced
//      epilogue (p=0 lanes own rows 0-1, p=1 rows 2-3), split accumulators.
//      Decoder + table kernels unchanged from R10.

#define BB    512
#define TT    1024
#define HID   100
#define VOCAB 62
#define NL    3
#define ROWS  4
#define NCTA  (BB / ROWS)       // 128
#define NTHR  256

// ---- shared memory layout (floats) ----
#define OFF_WH1  0
#define OFF_WI2  10000
#define OFF_WH2  20000
#define OFF_WI3  30000
#define OFF_WH3  40000
#define OFF_H    50000          // [2 buf][NL][ROWS][HID] = 2400
#define SMEM_FLOATS (OFF_H + 2 * NL * ROWS * HID)   // 52,400 -> 209,600 B

typedef unsigned long long ull;

__device__ float g_table[VOCAB * HID];            // emb@Wi1^T + b_ih1 + b_hh1
__device__ float g_h3[(size_t)BB * TT * HID];     // h3 stream (200 MB)

// ---------------------------------------------------------------------------
__global__ void table_kernel(const float* __restrict__ emb,
                             const float* __restrict__ W_ih,
                             const float* __restrict__ b_ih,
                             const float* __restrict__ b_hh) {
    int v = blockIdx.x;
    int j = threadIdx.x;
    if (j >= HID) return;
    float acc = b_ih[j] + b_hh[j];
    const float* e = emb + v * HID;
    const float* w = W_ih + j * HID;
#pragma unroll
    for (int k = 0; k < HID; k++) acc += e[k] * w[k];
    g_table[v * HID + j] = acc;
}

// ---------------------------------------------------------------------------
__device__ __forceinline__ void fma2(ull& acc, ull a, ull b) {
    asm("fma.rn.f32x2 %0, %1, %2, %3;" : "=l"(acc) : "l"(a), "l"(b), "l"(acc));
}
__device__ __forceinline__ float hadd2(ull a) {
    float lo = __uint_as_float((unsigned)a);
    float hi = __uint_as_float((unsigned)(a >> 32));
    return lo + hi;
}
__device__ __forceinline__ ulonglong2 ldv(const float* pf) {
    return *reinterpret_cast<const ulonglong2*>(pf);
}
__device__ __forceinline__ float tanho(float x) {
    float e = __expf(2.0f * x);
    return 1.0f - __fdividef(2.0f, e + 1.0f);
}

// ---------------------------------------------------------------------------
__global__ __launch_bounds__(NTHR, 1)
void rnn_kernel(const int*   __restrict__ ids,
                const float* __restrict__ W_ih,
                const float* __restrict__ W_hh,
                const float* __restrict__ b_ih,
                const float* __restrict__ b_hh,
                float* __restrict__ hidden) {
    extern __shared__ float s[];
    const int tid  = threadIdx.x;
    const int wid  = tid >> 5;
    const int lane = tid & 31;
    const int p    = lane >> 4;        // k-half: 0 -> [0,52), 1 -> [52,100)
    const int m    = lane & 15;        // neuron slot (0..12 active)
    const int b0   = blockIdx.x * ROWS;
    const int kh   = p * 52;
    const int r0   = p * 2;            // my epilogue rows: r0, r0+1
    const int r1   = r0 + 1;

    const int  j   = wid * 13 + m;
    const int  jc  = (j < HID) ? j : (HID - 1);
    const bool act = (m < 13) && (j < HID);

    // ---- stage weights ----
    for (int i = tid; i < HID * HID; i += NTHR) {
        s[OFF_WH1 + i] = W_hh[i];
        s[OFF_WI2 + i] = W_ih[1 * HID * HID + i];
        s[OFF_WH2 + i] = W_hh[1 * HID * HID + i];
        s[OFF_WI3 + i] = W_ih[2 * HID * HID + i];
        s[OFF_WH3 + i] = W_hh[2 * HID * HID + i];
    }
    for (int i = tid; i < 2 * NL * ROWS * HID; i += NTHR) s[OFF_H + i] = 0.0f;

    const float rb2 = b_ih[1 * HID + jc] + b_hh[1 * HID + jc];
    const float rb3 = b_ih[2 * HID + jc] + b_hh[2 * HID + jc];
    __syncthreads();

    const float* w1 = s + OFF_WH1 + jc * HID + kh;
    const float* i2 = s + OFF_WI2 + jc * HID + kh;
    const float* w2 = s + OFF_WH2 + jc * HID + kh;
    const float* i3 = s + OFF_WI3 + jc * HID + kh;
    const float* w3 = s + OFF_WH3 + jc * HID + kh;

    // token prefetch for my 2 rows
    int tokA = ids[(b0 + r0) * TT];
    int tokB = ids[(b0 + r1) * TT];

    for (int t = 0; t < TT; t++) {
        const int ro = t & 1, wo = ro ^ 1;
        const float* hr = s + OFF_H + ro * 1200;
        float*       hw = s + OFF_H + wo * 1200;

        // ================= layer 1 =================
        {
            const float tA = g_table[tokA * HID + jc];   // issue early
            const float tB = g_table[tokB * HID + jc];

            const float* h1 = hr + 0 + kh;               // h1(t-1), + r*100
            ull a0 = 0, a1 = 0, a2 = 0, a3 = 0;
#pragma unroll
            for (int kc = 0; kc < 13; kc++) {
                if (kc < 12 || p == 0) {
                    ulonglong2 w = ldv(w1 + 4 * kc);
                    ulonglong2 h;
                    h = ldv(h1 + 0 * HID + 4 * kc); fma2(a0, w.x, h.x); fma2(a0, w.y, h.y);
                    h = ldv(h1 + 1 * HID + 4 * kc); fma2(a1, w.x, h.x); fma2(a1, w.y, h.y);
                    h = ldv(h1 + 2 * HID + 4 * kc); fma2(a2, w.x, h.x); fma2(a2, w.y, h.y);
                    h = ldv(h1 + 3 * HID + 4 * kc); fma2(a3, w.x, h.x); fma2(a3, w.y, h.y);
                }
            }
            float v0 = hadd2(a0), v1 = hadd2(a1), v2 = hadd2(a2), v3 = hadd2(a3);
            float sA = p ? v0 : v2, sB = p ? v1 : v3;
            float rA = __shfl_xor_sync(0xffffffffu, sA, 16);
            float rB = __shfl_xor_sync(0xffffffffu, sB, 16);
            float s0 = (p ? v2 : v0) + rA;
            float s1 = (p ? v3 : v1) + rB;
            if (act) {
                hw[0 + r0 * HID + j] = tanho(tA + s0);
                hw[0 + r1 * HID + j] = tanho(tB + s1);
            }
        }
        __syncthreads();

        // ================= layer 2 =================
        {
            const float* h1 = hw + 0   + kh;             // h1(t)
            const float* h2 = hr + 400 + kh;             // h2(t-1)
            ull a0 = 0, a1 = 0, a2 = 0, a3 = 0;          // wi2 chains
            ull c0 = 0, c1 = 0, c2 = 0, c3 = 0;          // wh2 chains
#pragma unroll
            for (int kc = 0; kc < 13; kc++) {
                if (kc < 12 || p == 0) {
                    ulonglong2 wa = ldv(i2 + 4 * kc);
                    ulonglong2 wb = ldv(w2 + 4 * kc);
                    ulonglong2 ha, hb;
                    ha = ldv(h1 + 0 * HID + 4 * kc); hb = ldv(h2 + 0 * HID + 4 * kc);
                    fma2(a0, wa.x, ha.x); fma2(a0, wa.y, ha.y);
                    fma2(c0, wb.x, hb.x); fma2(c0, wb.y, hb.y);
                    ha = ldv(h1 + 1 * HID + 4 * kc); hb = ldv(h2 + 1 * HID + 4 * kc);
                    fma2(a1, wa.x, ha.x); fma2(a1, wa.y, ha.y);
                    fma2(c1, wb.x, hb.x); fma2(c1, wb.y, hb.y);
                    ha = ldv(h1 + 2 * HID + 4 * kc); hb = ldv(h2 + 2 * HID + 4 * kc);
                    fma2(a2, wa.x, ha.x); fma2(a2, wa.y, ha.y);
                    fma2(c2, wb.x, hb.x); fma2(c2, wb.y, hb.y);
                    ha = ldv(h1 + 3 * HID + 4 * kc); hb = ldv(h2 + 3 * HID + 4 * kc);
                    fma2(a3, wa.x, ha.x); fma2(a3, wa.y, ha.y);
                    fma2(c3, wb.x, hb.x); fma2(c3, wb.y, hb.y);
                }
            }
            float v0 = hadd2(a0) + hadd2(c0), v1 = hadd2(a1) + hadd2(c1);
            float v2 = hadd2(a2) + hadd2(c2), v3 = hadd2(a3) + hadd2(c3);
            float sA = p ? v0 : v2, sB = p ? v1 : v3;
            float rA = __shfl_xor_sync(0xffffffffu, sA, 16);
            float rB = __shfl_xor_sync(0xffffffffu, sB, 16);
            float s0 = (p ? v2 : v0) + rA;
            float s1 = (p ? v3 : v1) + rB;
            if (act) {
                hw[400 + r0 * HID + j] = tanho(rb2 + s0);
                hw[400 + r1 * HID + j] = tanho(rb2 + s1);
            }
        }
        __syncthreads();

        // ================= layer 3 (+ h3 stream, + tok prefetch) ==========
        {
            const int tn = (t + 1 < TT) ? (t + 1) : (TT - 1);
            tokA = ids[(b0 + r0) * TT + tn];
            tokB = ids[(b0 + r1) * TT + tn];

            const float* h2 = hw + 400 + kh;             // h2(t)
            const float* h3 = hr + 800 + kh;             // h3(t-1)
            ull a0 = 0, a1 = 0, a2 = 0, a3 = 0;
            ull c0 = 0, c1 = 0, c2 = 0, c3 = 0;
#pragma unroll
            for (int kc = 0; kc < 13; kc++) {
                if (kc < 12 || p == 0) {
                    ulonglong2 wa = ldv(i3 + 4 * kc);
                    ulonglong2 wb = ldv(w3 + 4 * kc);
                    ulonglong2 ha, hb;
                    ha = ldv(h2 + 0 * HID + 4 * kc); hb = ldv(h3 + 0 * HID + 4 * kc);
                    fma2(a0, wa.x, ha.x); fma2(a0, wa.y, ha.y);
                    fma2(c0, wb.x, hb.x); fma2(c0, wb.y, hb.y);
                    ha = ldv(h2 + 1 * HID + 4 * kc); hb = ldv(h3 + 1 * HID + 4 * kc);
                    fma2(a1, wa.x, ha.x); fma2(a1, wa.y, ha.y);
                    fma2(c1, wb.x, hb.x); fma2(c1, wb.y, hb.y);
                    ha = ldv(h2 + 2 * HID + 4 * kc); hb = ldv(h3 + 2 * HID + 4 * kc);
                    fma2(a2, wa.x, ha.x); fma2(a2, wa.y, ha.y);
                    fma2(c2, wb.x, hb.x); fma2(c2, wb.y, hb.y);
                    ha = ldv(h2 + 3 * HID + 4 * kc); hb = ldv(h3 + 3 * HID + 4 * kc);
                    fma2(a3, wa.x, ha.x); fma2(a3, wa.y, ha.y);
                    fma2(c3, wb.x, hb.x); fma2(c3, wb.y, hb.y);
                }
            }
            float v0 = hadd2(a0) + hadd2(c0), v1 = hadd2(a1) + hadd2(c1);
            float v2 = hadd2(a2) + hadd2(c2), v3 = hadd2(a3) + hadd2(c3);
            float sA = p ? v0 : v2, sB = p ? v1 : v3;
            float rA = __shfl_xor_sync(0xffffffffu, sA, 16);
            float rB = __shfl_xor_sync(0xffffffffu, sB, 16);
            float s0 = (p ? v2 : v0) + rA;
            float s1 = (p ? v3 : v1) + rB;
            if (act) {
                float o0 = tanho(rb3 + s0);
                float o1 = tanho(rb3 + s1);
                hw[800 + r0 * HID + j] = o0;
                hw[800 + r1 * HID + j] = o1;
                g_h3[((size_t)(b0 + r0) * TT + t) * HID + j] = o0;
                g_h3[((size_t)(b0 + r1) * TT + t) * HID + j] = o1;
            }
        }
        __syncthreads();
    }

    // ---- final hidden [NL, B, HID]: step TT-1 wrote buffer 0 ----
    if (act) {
#pragma unroll
        for (int l = 0; l < NL; l++) {
            hidden[(size_t)(l * BB + b0 + r0) * HID + j] =
                s[OFF_H + l * 400 + r0 * HID + j];
            hidden[(size_t)(l * BB + b0 + r1) * HID + j] =
                s[OFF_H + l * 400 + r1 * HID + j];
        }
    }
}

// ---------------------------------------------------------------------------
// Decoder GEMM (unchanged from R10)
// ---------------------------------------------------------------------------
#define DT   256
#define GR   128
#define DS_W 0
#define DS_H 6208
#define DS_B 19008
#define DS_FLOATS 19072

__global__ __launch_bounds__(DT)
void dec_kernel(const float* __restrict__ W_dec,
                const float* __restrict__ b_dec,
                float* __restrict__ logits) {
    extern __shared__ float ds[];
    const int tid  = threadIdx.x;
    const int tile = blockIdx.x;

    float4* sw4 = reinterpret_cast<float4*>(ds + DS_W);
    const float4* wsrc = reinterpret_cast<const float4*>(W_dec);
    for (int i = tid; i < VOCAB * HID / 4; i += DT) sw4[i] = wsrc[i];

    float4* sh4 = reinterpret_cast<float4*>(ds + DS_H);
    const float4* hsrc = reinterpret_cast<const float4*>(g_h3 + (size_t)tile * GR * HID);
    for (int i = tid; i < GR * HID / 4; i += DT) sh4[i] = hsrc[i];

    for (int i = tid; i < VOCAB; i += DT) ds[DS_B + i] = b_dec[i];
    __syncthreads();

    const int r    = tid & 127;
    const int half = tid >> 7;
    const int jb   = half * 31;

    ull acc[31];
#pragma unroll
    for (int jj = 0; jj < 31; jj++) acc[jj] = 0ull;

    const float* hrow = ds + DS_H + r * HID;
    for (int kc = 0; kc < 25; kc++) {
        ulonglong2 hq = ldv(hrow + 4 * kc);
#pragma unroll
        for (int jj = 0; jj < 31; jj++) {
            ulonglong2 wq = ldv(ds + DS_W + (jb + jj) * HID + 4 * kc);
            fma2(acc[jj], wq.x, hq.x);
            fma2(acc[jj], wq.y, hq.y);
        }
    }

    float* out = logits + ((size_t)tile * GR + r) * VOCAB + jb;
#pragma unroll
    for (int jj = 0; jj < 31; jj++)
        out[jj] = ds[DS_B + jb + jj] + hadd2(acc[jj]);
}

// ---------------------------------------------------------------------------
extern "C" void kernel_launch(void* const* d_in, const int* in_sizes, int n_in,
                              void* d_out, int out_size) {
    const int*   ids   = (const int*)  d_in[0];
    const float* emb   = (const float*)d_in[1];
    const float* W_ih  = (const float*)d_in[2];
    const float* W_hh  = (const float*)d_in[3];
    const float* b_ih  = (const float*)d_in[4];
    const float* b_hh  = (const float*)d_in[5];
    const float* W_dec = (const float*)d_in[6];
    const float* b_dec = (const float*)d_in[7];

    float* out    = (float*)d_out;
    float* logits = out;
    float* hidden = out + ((size_t)out_size - (size_t)NL * BB * HID);

    table_kernel<<<VOCAB, 128>>>(emb, W_ih, b_ih, b_hh);

    size_t smem = SMEM_FLOATS * sizeof(float);
    cudaFuncSetAttribute(rnn_kernel, cudaFuncAttributeMaxDynamicSharedMemorySize,
                         (int)smem);
    rnn_kernel<<<NCTA, NTHR, smem>>>(ids, W_ih, W_hh, b_ih, b_hh, hidden);

    size_t dsmem = DS_FLOATS * sizeof(float);
    cudaFuncSetAttribute(dec_kernel, cudaFuncAttributeMaxDynamicSharedMemorySize,
                         (int)dsmem);
    dec_kernel<<<(BB * TT) / GR, DT, dsmem>>>(W_dec, b_dec, logits);
}

// round 12
// speedup vs baseline: 1.1701x; 1.1701x over previous
#include <cuda_runtime.h>

// CharRNN: 3-layer tanh RNN, B=512, T=1024, HID=100, VOCAB=62.
// R12: R10 champion with phases merged 3 -> 2 per step, SAME cross-warp
//      scratch exchange (shfl proven worse in R5/R11):
//      Phase A: L2(t) + L1(t+1) fused (shared h1 loads); balanced epilogue
//               (p0 finalizes h2, p1 finalizes h1).
//      Phase B: L3(t); epilogue split by rows (p0: rows 0-1, p1: rows 2-3).
//      4 barriers + 2 scratch rounds/step (was 6 + 3). Single in-place h
//      buffer. Decoder + table kernels unchanged from R10.

#define BB    512
#define TT    1024
#define HID   100
#define VOCAB 62
#define NL    3
#define ROWS  4
#define NCTA  (BB / ROWS)       // 128
#define NTHR  256

// ---- shared memory layout (floats) ----
#define OFF_WH1  0
#define OFF_WI2  10000
#define OFF_WH2  20000
#define OFF_WI3  30000
#define OFF_WH3  40000
#define OFF_SCR  50000          // 1024 floats (two 512-float regions)
#define OFF_H1   51024          // 4x100
#define OFF_H2   51424
#define OFF_H3   51824
#define SMEM_FLOATS 52224       // 208,896 bytes

typedef unsigned long long ull;

__device__ float g_table[VOCAB * HID];            // emb@Wi1^T + b_ih1 + b_hh1
__device__ float g_h3[(size_t)BB * TT * HID];     // h3 stream (200 MB)

// ---------------------------------------------------------------------------
__global__ void table_kernel(const float* __restrict__ emb,
                             const float* __restrict__ W_ih,
                             const float* __restrict__ b_ih,
                             const float* __restrict__ b_hh) {
    int v = blockIdx.x;
    int j = threadIdx.x;
    if (j >= HID) return;
    float acc = b_ih[j] + b_hh[j];
    const float* e = emb + v * HID;
    const float* w = W_ih + j * HID;
#pragma unroll
    for (int k = 0; k < HID; k++) acc += e[k] * w[k];
    g_table[v * HID + j] = acc;
}

// ---------------------------------------------------------------------------
__device__ __forceinline__ void fma2(ull& acc, ull a, ull b) {
    asm("fma.rn.f32x2 %0, %1, %2, %3;" : "=l"(acc) : "l"(a), "l"(b), "l"(acc));
}
__device__ __forceinline__ float hadd2(ull a) {
    float lo = __uint_as_float((unsigned)a);
    float hi = __uint_as_float((unsigned)(a >> 32));
    return lo + hi;
}
__device__ __forceinline__ ulonglong2 ldv(const float* pf) {
    return *reinterpret_cast<const ulonglong2*>(pf);
}
__device__ __forceinline__ float tanho(float x) {
    float e = __expf(2.0f * x);
    return 1.0f - __fdividef(2.0f, e + 1.0f);
}

// fused phase-A dot over [KB,KE): a2[r] += wi2.h1_r + wh2.h2_r ; a1[r] += wh1.h1_r
template <int KB, int KE>
__device__ __forceinline__ void dotA(const float* __restrict__ wi2row,
                                     const float* __restrict__ wh2row,
                                     const float* __restrict__ wh1row,
                                     const float* __restrict__ h1b,
                                     const float* __restrict__ h2b,
                                     ull a2[ROWS], ull a1[ROWS]) {
#pragma unroll
    for (int kc = KB; kc < KE; kc++) {
        ulonglong2 wi = ldv(wi2row + kc * 4);
        ulonglong2 wh = ldv(wh2row + kc * 4);
        ulonglong2 w1 = ldv(wh1row + kc * 4);
#pragma unroll
        for (int r = 0; r < ROWS; r++) {
            ulonglong2 h1 = ldv(h1b + r * HID + kc * 4);
            ulonglong2 h2 = ldv(h2b + r * HID + kc * 4);
            fma2(a2[r], wi.x, h1.x); fma2(a2[r], wi.y, h1.y);
            fma2(a2[r], wh.x, h2.x); fma2(a2[r], wh.y, h2.y);
            fma2(a1[r], w1.x, h1.x); fma2(a1[r], w1.y, h1.y);
        }
    }
}

// phase-B dot: acc[r] += wa.ha_r + wb.hb_r
template <int KB, int KE>
__device__ __forceinline__ void dotB(const float* __restrict__ warow,
                                     const float* __restrict__ wbrow,
                                     const float* __restrict__ habase,
                                     const float* __restrict__ hbbase,
                                     ull acc[ROWS]) {
#pragma unroll
    for (int kc = KB; kc < KE; kc++) {
        ulonglong2 wa = ldv(warow + kc * 4);
        ulonglong2 wb = ldv(wbrow + kc * 4);
#pragma unroll
        for (int r = 0; r < ROWS; r++) {
            ulonglong2 ha = ldv(habase + r * HID + kc * 4);
            ulonglong2 hb = ldv(hbbase + r * HID + kc * 4);
            fma2(acc[r], wa.x, ha.x); fma2(acc[r], wa.y, ha.y);
            fma2(acc[r], wb.x, hb.x); fma2(acc[r], wb.y, hb.y);
        }
    }
}

// ---------------------------------------------------------------------------
__global__ __launch_bounds__(NTHR, 1)
void rnn_kernel(const int*   __restrict__ ids,
                const float* __restrict__ W_ih,
                const float* __restrict__ W_hh,
                const float* __restrict__ b_ih,
                const float* __restrict__ b_hh,
                float* __restrict__ hidden) {
    extern __shared__ float s[];
    const int tid = threadIdx.x;
    const int p   = tid >> 7;       // k-split group: 0 or 1
    const int j   = tid & 127;      // neuron index
    const int b0  = blockIdx.x * ROWS;
    const bool act = (j < HID);

    // ---- stage weights ----
    for (int i = tid; i < HID * HID; i += NTHR) {
        s[OFF_WH1 + i] = W_hh[i];
        s[OFF_WI2 + i] = W_ih[1 * HID * HID + i];
        s[OFF_WH2 + i] = W_hh[1 * HID * HID + i];
        s[OFF_WI3 + i] = W_ih[2 * HID * HID + i];
        s[OFF_WH3 + i] = W_hh[2 * HID * HID + i];
    }
    for (int i = tid; i < ROWS * HID; i += NTHR) {
        s[OFF_H2 + i] = 0.0f;
        s[OFF_H3 + i] = 0.0f;
    }

    const float rb2 = b_ih[1 * HID + (act ? j : 0)] + b_hh[1 * HID + (act ? j : 0)];
    const float rb3 = b_ih[2 * HID + (act ? j : 0)] + b_hh[2 * HID + (act ? j : 0)];
    const int jc = act ? j : (HID - 1);

    const float* wh1 = s + OFF_WH1 + jc * HID;
    const float* wi2 = s + OFF_WI2 + jc * HID;
    const float* wh2 = s + OFF_WH2 + jc * HID;
    const float* wi3 = s + OFF_WI3 + jc * HID;
    const float* wh3 = s + OFF_WH3 + jc * HID;

    // ---- pre-loop: h1(0) = tanh(table[tok0]); prefetch tok(1) ----
    int tok[ROWS];
    if (p == 0 && act) {
#pragma unroll
        for (int r = 0; r < ROWS; r++) {
            int t0 = ids[(b0 + r) * TT];
            s[OFF_H1 + r * HID + j] = tanho(g_table[t0 * HID + j]);
        }
    }
#pragma unroll
    for (int r = 0; r < ROWS; r++) tok[r] = ids[(b0 + r) * TT + 1];
    __syncthreads();

    for (int t = 0; t < TT; t++) {
        // ========= Phase A: L2(t) + L1(t+1) =========
        {
            // table inputs for L1(t+1) — finalized by p1; issue LDG early
            float tbl[ROWS];
            if (p == 1 && act) {
#pragma unroll
                for (int r = 0; r < ROWS; r++) tbl[r] = g_table[tok[r] * HID + j];
            }

            ull a2[ROWS] = {0, 0, 0, 0};
            ull a1[ROWS] = {0, 0, 0, 0};
            if (act) {
                if (p == 0) dotA<0, 13>(wi2, wh2, wh1, s + OFF_H1, s + OFF_H2, a2, a1);
                else        dotA<13, 25>(wi2, wh2, wh1, s + OFF_H1, s + OFF_H2, a2, a1);
            }
            float4 v2, v1;
            v2.x = hadd2(a2[0]); v2.y = hadd2(a2[1]);
            v2.z = hadd2(a2[2]); v2.w = hadd2(a2[3]);
            v1.x = hadd2(a1[0]); v1.y = hadd2(a1[1]);
            v1.z = hadd2(a1[2]); v1.w = hadd2(a1[3]);
            // exchange: p0 sends L1 partials, p1 sends L2 partials
            if (act) {
                if (p == 0) *reinterpret_cast<float4*>(&s[OFF_SCR + 512 + 4 * j]) = v1;
                else        *reinterpret_cast<float4*>(&s[OFF_SCR + 4 * j])       = v2;
            }
            __syncthreads();
            if (act) {
                if (p == 0) {   // finalize h2(t)
                    float4 o = *reinterpret_cast<const float4*>(&s[OFF_SCR + 4 * j]);
                    s[OFF_H2 + 0 * HID + j] = tanho(rb2 + v2.x + o.x);
                    s[OFF_H2 + 1 * HID + j] = tanho(rb2 + v2.y + o.y);
                    s[OFF_H2 + 2 * HID + j] = tanho(rb2 + v2.z + o.z);
                    s[OFF_H2 + 3 * HID + j] = tanho(rb2 + v2.w + o.w);
                } else if (t + 1 < TT) {   // finalize h1(t+1)
                    float4 o = *reinterpret_cast<const float4*>(&s[OFF_SCR + 512 + 4 * j]);
                    s[OFF_H1 + 0 * HID + j] = tanho(tbl[0] + v1.x + o.x);
                    s[OFF_H1 + 1 * HID + j] = tanho(tbl[1] + v1.y + o.y);
                    s[OFF_H1 + 2 * HID + j] = tanho(tbl[2] + v1.z + o.z);
                    s[OFF_H1 + 3 * HID + j] = tanho(tbl[3] + v1.w + o.w);
                }
            }
            __syncthreads();
        }

        // ========= Phase B: L3(t) (+ h3 stream, + tok prefetch) =========
        {
            const int tn = (t + 2 < TT) ? (t + 2) : (TT - 1);
#pragma unroll
            for (int r = 0; r < ROWS; r++) tok[r] = ids[(b0 + r) * TT + tn];

            ull a[ROWS] = {0, 0, 0, 0};
            if (act) {
                if (p == 0) dotB<0, 13>(wi3, wh3, s + OFF_H2, s + OFF_H3, a);
                else        dotB<13, 25>(wi3, wh3, s + OFF_H2, s + OFF_H3, a);
            }
            float4 v;
            v.x = hadd2(a[0]); v.y = hadd2(a[1]);
            v.z = hadd2(a[2]); v.w = hadd2(a[3]);
            // exchange: p0 sends rows 2-3 partials, p1 sends rows 0-1
            if (act) {
                if (p == 0) *reinterpret_cast<float2*>(&s[OFF_SCR + 2 * j]) =
                    make_float2(v.z, v.w);
                else        *reinterpret_cast<float2*>(&s[OFF_SCR + 512 + 2 * j]) =
                    make_float2(v.x, v.y);
            }
            __syncthreads();
            if (act) {
                if (p == 0) {   // finalize rows 0-1
                    float2 o = *reinterpret_cast<const float2*>(&s[OFF_SCR + 512 + 2 * j]);
                    float o0 = tanho(rb3 + v.x + o.x);
                    float o1 = tanho(rb3 + v.y + o.y);
                    s[OFF_H3 + 0 * HID + j] = o0;
                    s[OFF_H3 + 1 * HID + j] = o1;
                    g_h3[((size_t)(b0 + 0) * TT + t) * HID + j] = o0;
                    g_h3[((size_t)(b0 + 1) * TT + t) * HID + j] = o1;
                } else {        // finalize rows 2-3
                    float2 o = *reinterpret_cast<const float2*>(&s[OFF_SCR + 2 * j]);
                    float o2 = tanho(rb3 + v.z + o.x);
                    float o3 = tanho(rb3 + v.w + o.y);
                    s[OFF_H3 + 2 * HID + j] = o2;
                    s[OFF_H3 + 3 * HID + j] = o3;
                    g_h3[((size_t)(b0 + 2) * TT + t) * HID + j] = o2;
                    g_h3[((size_t)(b0 + 3) * TT + t) * HID + j] = o3;
                }
            }
            __syncthreads();
        }
    }

    // ---- final hidden states: [NL, B, HID] (single buffer, all at TT-1) ----
    for (int i = tid; i < NL * ROWS * HID; i += NTHR) {
        const int l = i / (ROWS * HID);
        const int rem = i - l * (ROWS * HID);
        const int r = rem / HID;
        const int jj = rem - r * HID;
        hidden[(size_t)(l * BB + b0 + r) * HID + jj] = s[OFF_H1 + l * 400 + r * HID + jj];
    }
}

// ---------------------------------------------------------------------------
// Decoder GEMM (unchanged from R10)
// ---------------------------------------------------------------------------
#define DT   256
#define GR   128
#define DS_W 0
#define DS_H 6208
#define DS_B 19008
#define DS_FLOATS 19072

__global__ __launch_bounds__(DT)
void dec_kernel(const float* __restrict__ W_dec,
                const float* __restrict__ b_dec,
                float* __restrict__ logits) {
    extern __shared__ float ds[];
    const int tid  = threadIdx.x;
    const int tile = blockIdx.x;

    float4* sw4 = reinterpret_cast<float4*>(ds + DS_W);
    const float4* wsrc = reinterpret_cast<const float4*>(W_dec);
    for (int i = tid; i < VOCAB * HID / 4; i += DT) sw4[i] = wsrc[i];

    float4* sh4 = reinterpret_cast<float4*>(ds + DS_H);
    const float4* hsrc = reinterpret_cast<const float4*>(g_h3 + (size_t)tile * GR * HID);
    for (int i = tid; i < GR * HID / 4; i += DT) sh4[i] = hsrc[i];

    for (int i = tid; i < VOCAB; i += DT) ds[DS_B + i] = b_dec[i];
    __syncthreads();

    const int r    = tid & 127;
    const int half = tid >> 7;
    const int jb   = half * 31;

    ull acc[31];
#pragma unroll
    for (int jj = 0; jj < 31; jj++) acc[jj] = 0ull;

    const float* hrow = ds + DS_H + r * HID;
    for (int kc = 0; kc < 25; kc++) {
        ulonglong2 hq = ldv(hrow + 4 * kc);
#pragma unroll
        for (int jj = 0; jj < 31; jj++) {
            ulonglong2 wq = ldv(ds + DS_W + (jb + jj) * HID + 4 * kc);
            fma2(acc[jj], wq.x, hq.x);
            fma2(acc[jj], wq.y, hq.y);
        }
    }

    float* out = logits + ((size_t)tile * GR + r) * VOCAB + jb;
#pragma unroll
    for (int jj = 0; jj < 31; jj++)
        out[jj] = ds[DS_B + jb + jj] + hadd2(acc[jj]);
}

// ---------------------------------------------------------------------------
extern "C" void kernel_launch(void* const* d_in, const int* in_sizes, int n_in,
                              void* d_out, int out_size) {
    const int*   ids   = (const int*)  d_in[0];
    const float* emb   = (const float*)d_in[1];
    const float* W_ih  = (const float*)d_in[2];
    const float* W_hh  = (const float*)d_in[3];
    const float* b_ih  = (const float*)d_in[4];
    const float* b_hh  = (const float*)d_in[5];
    const float* W_dec = (const float*)d_in[6];
    const float* b_dec = (const float*)d_in[7];

    float* out    = (float*)d_out;
    float* logits = out;
    float* hidden = out + ((size_t)out_size - (size_t)NL * BB * HID);

    table_kernel<<<VOCAB, 128>>>(emb, W_ih, b_ih, b_hh);

    size_t smem = SMEM_FLOATS * sizeof(float);
    cudaFuncSetAttribute(rnn_kernel, cudaFuncAttributeMaxDynamicSharedMemorySize,
                         (int)smem);
    rnn_kernel<<<NCTA, NTHR, smem>>>(ids, W_ih, W_hh, b_ih, b_hh, hidden);

    size_t dsmem = DS_FLOATS * sizeof(float);
    cudaFuncSetAttribute(dec_kernel, cudaFuncAttributeMaxDynamicSharedMemorySize,
                         (int)dsmem);
    dec_kernel<<<(BB * TT) / GR, DT, dsmem>>>(W_dec, b_dec, logits);
}

// round 14
// speedup vs baseline: 1.2633x; 1.0797x over previous
#include <cuda_runtime.h>

// CharRNN: 3-layer tanh RNN, B=512, T=1024, HID=100, VOCAB=62.
// R14: R13 + the race fix. R13's post-timing divergence was an init race:
//      zero-init of h buffers and the p0-group h1(0)=tanho(table) write hit
//      the same smem region with NO barrier between them. One __syncthreads()
//      fixes it. Everything else identical to R13:
//      - tick u computes h1(u+1), h2(u), h3(u-1) concurrently (software
//        pipeline; all inputs available at tick start; homogeneous work)
//      - 1 scratch-exchange round + 2 barriers per tick
//      - fused dot shares h1 loads (Wh1,Wi2) and h2 loads (Wh2,Wi3)
//      - balanced epilogue: p0 finalizes rows 0-1, p1 rows 2-3, all layers
//      - decoder offloaded to separate GEMM kernel.

#define BB    512
#define TT    1024
#define HID   100
#define VOCAB 62
#define NL    3
#define ROWS  4
#define NCTA  (BB / ROWS)       // 128
#define NTHR  256

// ---- shared memory layout (floats) ----
#define OFF_WH1  0
#define OFF_WI2  10000
#define OFF_WH2  20000
#define OFF_WI3  30000
#define OFF_WH3  40000
#define OFF_SCR  50000          // [group][layer][256]: 2*3*256 = 1536
#define OFF_H1   51536          // 4x100  (single buffer, in-place)
#define OFF_H2   51936
#define OFF_H3   52336
#define SMEM_FLOATS 52736       // 210,944 bytes

typedef unsigned long long ull;

__device__ float g_table[VOCAB * HID];            // emb@Wi1^T + b_ih1 + b_hh1
__device__ float g_h3[(size_t)BB * TT * HID];     // h3 stream (200 MB)

// ---------------------------------------------------------------------------
__global__ void table_kernel(const float* __restrict__ emb,
                             const float* __restrict__ W_ih,
                             const float* __restrict__ b_ih,
                             const float* __restrict__ b_hh) {
    int v = blockIdx.x;
    int j = threadIdx.x;
    if (j >= HID) return;
    float acc = b_ih[j] + b_hh[j];
    const float* e = emb + v * HID;
    const float* w = W_ih + j * HID;
#pragma unroll
    for (int k = 0; k < HID; k++) acc += e[k] * w[k];
    g_table[v * HID + j] = acc;
}

// ---------------------------------------------------------------------------
__device__ __forceinline__ void fma2(ull& acc, ull a, ull b) {
    asm("fma.rn.f32x2 %0, %1, %2, %3;" : "=l"(acc) : "l"(a), "l"(b), "l"(acc));
}
__device__ __forceinline__ float hadd2(ull a) {
    float lo = __uint_as_float((unsigned)a);
    float hi = __uint_as_float((unsigned)(a >> 32));
    return lo + hi;
}
__device__ __forceinline__ ulonglong2 ldv(const float* pf) {
    return *reinterpret_cast<const ulonglong2*>(pf);
}
__device__ __forceinline__ float tanho(float x) {
    float e = __expf(2.0f * x);
    return 1.0f - __fdividef(2.0f, e + 1.0f);
}

// fused 3-layer partial dot over quad range [KB,KE):
//   a1[r] += wh1 . h1_r
//   a2[r] += wi2 . h1_r + wh2 . h2_r
//   a3[r] += wi3 . h2_r + wh3 . h3_r
template <int KB, int KE>
__device__ __forceinline__ void dotF(const float* __restrict__ wh1row,
                                     const float* __restrict__ wi2row,
                                     const float* __restrict__ wh2row,
                                     const float* __restrict__ wi3row,
                                     const float* __restrict__ wh3row,
                                     const float* __restrict__ h1b,
                                     const float* __restrict__ h2b,
                                     const float* __restrict__ h3b,
                                     ull a1[ROWS], ull a2[ROWS], ull a3[ROWS]) {
#pragma unroll
    for (int kc = KB; kc < KE; kc++) {
        ulonglong2 w1 = ldv(wh1row + kc * 4);
        ulonglong2 wi = ldv(wi2row + kc * 4);
        ulonglong2 wh = ldv(wh2row + kc * 4);
        ulonglong2 vi = ldv(wi3row + kc * 4);
        ulonglong2 vh = ldv(wh3row + kc * 4);
#pragma unroll
        for (int r = 0; r < ROWS; r++) {
            ulonglong2 h1 = ldv(h1b + r * HID + kc * 4);
            ulonglong2 h2 = ldv(h2b + r * HID + kc * 4);
            ulonglong2 h3 = ldv(h3b + r * HID + kc * 4);
            fma2(a1[r], w1.x, h1.x); fma2(a1[r], w1.y, h1.y);
            fma2(a2[r], wi.x, h1.x); fma2(a2[r], wi.y, h1.y);
            fma2(a2[r], wh.x, h2.x); fma2(a2[r], wh.y, h2.y);
            fma2(a3[r], vi.x, h2.x); fma2(a3[r], vi.y, h2.y);
            fma2(a3[r], vh.x, h3.x); fma2(a3[r], vh.y, h3.y);
        }
    }
}

// ---------------------------------------------------------------------------
__global__ __launch_bounds__(NTHR, 1)
void rnn_kernel(const int*   __restrict__ ids,
                const float* __restrict__ W_ih,
                const float* __restrict__ W_hh,
                const float* __restrict__ b_ih,
                const float* __restrict__ b_hh,
                float* __restrict__ hidden) {
    extern __shared__ float s[];
    const int tid = threadIdx.x;
    const int p   = tid >> 7;        // k-split group: 0 or 1
    const int j   = tid & 127;       // neuron index
    const int b0  = blockIdx.x * ROWS;
    const bool act = (j < HID);
    const int jc  = act ? j : (HID - 1);
    const int r0  = 2 * p;           // rows I finalize: r0, r0+1
    const int r1  = r0 + 1;
    const int so  = 2 - 2 * p;       // rows I send (other group's rows)

    // ---- stage weights + zero h buffers ----
    for (int i = tid; i < HID * HID; i += NTHR) {
        s[OFF_WH1 + i] = W_hh[i];
        s[OFF_WI2 + i] = W_ih[1 * HID * HID + i];
        s[OFF_WH2 + i] = W_hh[1 * HID * HID + i];
        s[OFF_WI3 + i] = W_ih[2 * HID * HID + i];
        s[OFF_WH3 + i] = W_hh[2 * HID * HID + i];
    }
    for (int i = tid; i < ROWS * HID; i += NTHR) {
        s[OFF_H1 + i] = 0.0f;
        s[OFF_H2 + i] = 0.0f;
        s[OFF_H3 + i] = 0.0f;
    }

    const float rb2 = b_ih[1 * HID + jc] + b_hh[1 * HID + jc];
    const float rb3 = b_ih[2 * HID + jc] + b_hh[2 * HID + jc];

    const float* wh1 = s + OFF_WH1 + jc * HID;
    const float* wi2 = s + OFF_WI2 + jc * HID;
    const float* wh2 = s + OFF_WH2 + jc * HID;
    const float* wi3 = s + OFF_WI3 + jc * HID;
    const float* wh3 = s + OFF_WH3 + jc * HID;

    // RACE FIX (R13 bug): zero-init above and the tanho writes below touch
    // the same h1 region from different threads — must be ordered.
    __syncthreads();

    // ---- pre-loop: h1(0) = tanh(table[tok(0)]) ----
    if (p == 0 && act) {
#pragma unroll
        for (int r = 0; r < ROWS; r++) {
            int t0 = ids[(b0 + r) * TT];
            s[OFF_H1 + r * HID + j] = tanho(g_table[t0 * HID + j]);
        }
    }
    // tokens for time 1 (my finalize rows only)
    int tokA = ids[(b0 + r0) * TT + ((TT > 1) ? 1 : 0)];
    int tokB = ids[(b0 + r1) * TT + ((TT > 1) ? 1 : 0)];
    __syncthreads();

    // ======================= pipelined tick loop =======================
    // tick u: h1(u+1) [u<=TT-2], h2(u) [u<=TT-1], h3(u-1) [u>=1]
    for (int u = 0; u <= TT; u++) {
        // issue long-latency loads first (consumed in epilogue / next tick)
        const float tblA = g_table[tokA * HID + jc];
        const float tblB = g_table[tokB * HID + jc];
        const int tn = (u + 2 <= TT - 1) ? (u + 2) : (TT - 1);
        const int nA = ids[(b0 + r0) * TT + tn];
        const int nB = ids[(b0 + r1) * TT + tn];

        ull a1[ROWS] = {0, 0, 0, 0};
        ull a2[ROWS] = {0, 0, 0, 0};
        ull a3[ROWS] = {0, 0, 0, 0};
        if (act) {
            if (p == 0)
                dotF<0, 13>(wh1, wi2, wh2, wi3, wh3,
                            s + OFF_H1, s + OFF_H2, s + OFF_H3, a1, a2, a3);
            else
                dotF<13, 25>(wh1, wi2, wh2, wi3, wh3,
                             s + OFF_H1, s + OFF_H2, s + OFF_H3, a1, a2, a3);
        }
        float v1[ROWS], v2[ROWS], v3[ROWS];
#pragma unroll
        for (int r = 0; r < ROWS; r++) {
            v1[r] = hadd2(a1[r]); v2[r] = hadd2(a2[r]); v3[r] = hadd2(a3[r]);
        }

        // exchange: send my partials for the OTHER group's rows (so, so+1)
        if (act) {
            float* sc = s + OFF_SCR + p * 768;
            *reinterpret_cast<float2*>(&sc[0 * 256 + 2 * j]) = make_float2(v1[so], v1[so + 1]);
            *reinterpret_cast<float2*>(&sc[1 * 256 + 2 * j]) = make_float2(v2[so], v2[so + 1]);
            *reinterpret_cast<float2*>(&sc[2 * 256 + 2 * j]) = make_float2(v3[so], v3[so + 1]);
        }
        __syncthreads();

        if (act) {
            const float* oc = s + OFF_SCR + (1 - p) * 768;
            float2 o1 = *reinterpret_cast<const float2*>(&oc[0 * 256 + 2 * j]);
            float2 o2 = *reinterpret_cast<const float2*>(&oc[1 * 256 + 2 * j]);
            float2 o3 = *reinterpret_cast<const float2*>(&oc[2 * 256 + 2 * j]);

            if (u + 1 <= TT - 1) {          // h1(u+1), my rows
                s[OFF_H1 + r0 * HID + j] = tanho(tblA + v1[r0] + o1.x);
                s[OFF_H1 + r1 * HID + j] = tanho(tblB + v1[r1] + o1.y);
            }
            if (u <= TT - 1) {              // h2(u)
                s[OFF_H2 + r0 * HID + j] = tanho(rb2 + v2[r0] + o2.x);
                s[OFF_H2 + r1 * HID + j] = tanho(rb2 + v2[r1] + o2.y);
            }
            if (u >= 1) {                   // h3(u-1) + stream-out
                float q0 = tanho(rb3 + v3[r0] + o3.x);
                float q1 = tanho(rb3 + v3[r1] + o3.y);
                s[OFF_H3 + r0 * HID + j] = q0;
                s[OFF_H3 + r1 * HID + j] = q1;
                g_h3[((size_t)(b0 + r0) * TT + (u - 1)) * HID + j] = q0;
                g_h3[((size_t)(b0 + r1) * TT + (u - 1)) * HID + j] = q1;
            }
        }
        tokA = nA; tokB = nB;
        __syncthreads();
    }

    // ---- final hidden [NL, B, HID]: buffers hold h(TT-1) for all layers ----
    for (int i = tid; i < NL * ROWS * HID; i += NTHR) {
        const int l = i / (ROWS * HID);
        const int rem = i - l * (ROWS * HID);
        const int r = rem / HID;
        const int jj = rem - r * HID;
        hidden[(size_t)(l * BB + b0 + r) * HID + jj] =
            s[OFF_H1 + l * 400 + r * HID + jj];
    }
}

// ---------------------------------------------------------------------------
// Decoder GEMM (unchanged from R12)
// ---------------------------------------------------------------------------
#define DT   256
#define GR   128
#define DS_W 0
#define DS_H 6208
#define DS_B 19008
#define DS_FLOATS 19072

__global__ __launch_bounds__(DT)
void dec_kernel(const float* __restrict__ W_dec,
                const float* __restrict__ b_dec,
                float* __restrict__ logits) {
    extern __shared__ float ds[];
    const int tid  = threadIdx.x;
    const int tile = blockIdx.x;

    float4* sw4 = reinterpret_cast<float4*>(ds + DS_W);
    const float4* wsrc = reinterpret_cast<const float4*>(W_dec);
    for (int i = tid; i < VOCAB * HID / 4; i += DT) sw4[i] = wsrc[i];

    float4* sh4 = reinterpret_cast<float4*>(ds + DS_H);
    const float4* hsrc = reinterpret_cast<const float4*>(g_h3 + (size_t)tile * GR * HID);
    for (int i = tid; i < GR * HID / 4; i += DT) sh4[i] = hsrc[i];

    for (int i = tid; i < VOCAB; i += DT) ds[DS_B + i] = b_dec[i];
    __syncthreads();

    const int r    = tid & 127;
    const int half = tid >> 7;
    const int jb   = half * 31;

    ull acc[31];
#pragma unroll
    for (int jj = 0; jj < 31; jj++) acc[jj] = 0ull;

    const float* hrow = ds + DS_H + r * HID;
    for (int kc = 0; kc < 25; kc++) {
        ulonglong2 hq = ldv(hrow + 4 * kc);
#pragma unroll
        for (int jj = 0; jj < 31; jj++) {
            ulonglong2 wq = ldv(ds + DS_W + (jb + jj) * HID + 4 * kc);
            fma2(acc[jj], wq.x, hq.x);
            fma2(acc[jj], wq.y, hq.y);
        }
    }

    float* out = logits + ((size_t)tile * GR + r) * VOCAB + jb;
#pragma unroll
    for (int jj = 0; jj < 31; jj++)
        out[jj] = ds[DS_B + jb + jj] + hadd2(acc[jj]);
}

// ---------------------------------------------------------------------------
extern "C" void kernel_launch(void* const* d_in, const int* in_sizes, int n_in,
                              void* d_out, int out_size) {
    const int*   ids   = (const int*)  d_in[0];
    const float* emb   = (const float*)d_in[1];
    const float* W_ih  = (const float*)d_in[2];
    const float* W_hh  = (const float*)d_in[3];
    const float* b_ih  = (const float*)d_in[4];
    const float* b_hh  = (const float*)d_in[5];
    const float* W_dec = (const float*)d_in[6];
    const float* b_dec = (const float*)d_in[7];

    float* out    = (float*)d_out;
    float* logits = out;
    float* hidden = out + ((size_t)out_size - (size_t)NL * BB * HID);

    table_kernel<<<VOCAB, 128>>>(emb, W_ih, b_ih, b_hh);

    size_t smem = SMEM_FLOATS * sizeof(float);
    cudaFuncSetAttribute(rnn_kernel, cudaFuncAttributeMaxDynamicSharedMemorySize,
                         (int)smem);
    rnn_kernel<<<NCTA, NTHR, smem>>>(ids, W_ih, W_hh, b_ih, b_hh, hidden);

    size_t dsmem = DS_FLOATS * sizeof(float);
    cudaFuncSetAttribute(dec_kernel, cudaFuncAttributeMaxDynamicSharedMemorySize,
                         (int)dsmem);
    dec_kernel<<<(BB * TT) / GR, DT, dsmem>>>(W_dec, b_dec, logits);
}